// round 10
// baseline (speedup 1.0000x reference)
#include <cuda_runtime.h>
#include <math.h>

#define NBATCH 8
#define NPTS   131072
#define NGRP   30
#define NGB    (NBATCH*NGRP)   // 240
#define KNN    100
#define STRIDE 4369            // 131072/30
#define HB     2048
#define GPT    6               // groups per tile
#define GT     5               // tiles
#define PTC    16              // point chunks
#define CHUNK  (NPTS/PTC)      // 8192
#define NT     256             // scan threads
#define NTF    512             // selfin threads
#define MTGT   700.0f

#define SEGCAP 128             // per-(group,chunk) survivor segment
#define SELCAP (PTC*SEGCAP)    // 2048
#define SUBCAP 1024
#define FCAP   4096            // rescue/brute candidate buffer

#define SF_DYN ((5*FCAP + HB)*4)   // 88 KB

// -------- static device scratch --------
__device__ float    d_Ta[NGB];
__device__ unsigned d_segcnt[NGB][PTC];
__device__ float4   d_seg[NGB][PTC][SEGCAP];
__device__ double   d_gmean[NGB][3];
__device__ double   d_gcov[NGB][6];
__device__ float    d_dirs[NGB][3];
__device__ double   d_fs[NGB];
__device__ unsigned d_ticket;

__device__ __forceinline__ int d2bin_exp(float d2) {
    return (int)(__float_as_uint(d2) >> 21);
}

// ===========================================================================
// K1: scan (unchanged from R9). Radii via bisection on the closed-form
// noncentral distance CDF; survivors -> private segments.
// ===========================================================================
__global__ void __launch_bounds__(NT) scan_kernel(const float* __restrict__ pts_all) {
    __shared__ float ta[GPT], qxs[GPT], qys[GPT], qzs[GPT];
    __shared__ unsigned scnt[GPT];
    const int bidx = blockIdx.x;
    const int pc = bidx % PTC;
    const int gt = (bidx / PTC) % GT;
    const int b  = bidx / (PTC * GT);
    const float* __restrict__ pts = pts_all + (size_t)b * NPTS * 3;
    const float4* __restrict__ p4 = (const float4*)pts;
    const int gbase = b * NGRP + gt * GPT;
    const int tid = threadIdx.x;

    if (tid < GPT) {
        int ci = (gt*GPT + tid) * STRIDE;
        float qx = pts[3*ci], qy = pts[3*ci+1], qz = pts[3*ci+2];
        qxs[tid] = qx; qys[tid] = qy; qzs[tid] = qz;
        float rho = fmaxf(sqrtf(qx*qx + qy*qy + qz*qz), 0.02f);
        const float tgt = MTGT / (float)NPTS;
        const float irho = 0.3989423f / rho;
        float lo = 0.01f, hi = 6.0f;
        #pragma unroll 1
        for (int it = 0; it < 30; it++) {
            float s = 0.5f*(lo + hi);
            float a = s - rho, c = s + rho;
            float F = 0.5f*erff(a*0.70710678f) + 0.5f*erff(c*0.70710678f)
                    - (expf(-0.5f*a*a) - expf(-0.5f*c*c)) * irho;
            if (F >= tgt) hi = s; else lo = s;
        }
        ta[tid] = hi * hi;
        d_Ta[gbase + tid] = hi * hi;
        scnt[tid] = 0u;
    }
    if (bidx == 0 && tid == 0) d_ticket = 0u;
    __syncthreads();

    float qx[GPT], qy[GPT], qz[GPT], tta[GPT];
    #pragma unroll
    for (int j = 0; j < GPT; j++) { qx[j]=qxs[j]; qy[j]=qys[j]; qz[j]=qzs[j]; tta[j]=ta[j]; }

    const int q0 = pc * (CHUNK/4);
    for (int it = q0 + tid; it < q0 + CHUNK/4; it += NT) {
        float4 A = p4[3*it+0];
        float4 B = p4[3*it+1];
        float4 C = p4[3*it+2];
        float xs[4] = {A.x, A.w, B.z, C.y};
        float ys[4] = {A.y, B.x, B.w, C.z};
        float zs[4] = {A.z, B.y, C.x, C.w};
        #pragma unroll
        for (int k = 0; k < 4; k++) {
            #pragma unroll
            for (int j = 0; j < GPT; j++) {
                float dx = xs[k]-qx[j], dy = ys[k]-qy[j], dz = zs[k]-qz[j];
                float d2 = fmaf(dx, dx, fmaf(dy, dy, dz*dz));
                if (d2 < tta[j]) {
                    unsigned s = atomicAdd(&scnt[j], 1u);
                    if (s < SEGCAP)
                        d_seg[gbase + j][pc][s] = make_float4(xs[k], ys[k], zs[k],
                                                              __int_as_float(4*it + k));
                }
            }
        }
    }
    __syncthreads();
    if (tid < GPT) d_segcnt[gbase + tid][pc] = scnt[tid];
}

// ===========================================================================
// selfin shared state + helpers (NTF = 512 threads)
// ===========================================================================
struct SelSh {
    int      subSlot[SUBCAP];
    int      order[KNN];
    double   red[NTF];
    double   wsumd[4*9];
    double   accd[9];
    unsigned wsumu[16];
    unsigned offs[PTC+1];
    float    q2s[4];
    double   Dc;
    unsigned nsub;
    unsigned ncand;
    int      pivotS;
    int      gflag;
    float    sT2;
    int      lastb;
};

__device__ __forceinline__ double tree_red(double* red, int tid, double v) {
    red[tid] = v;
    __syncthreads();
    #pragma unroll
    for (int s = NTF/2; s > 0; s >>= 1) {
        if (tid < s) red[tid] += red[tid + s];
        __syncthreads();
    }
    double r = red[0];
    __syncthreads();
    return r;
}

// parallel pivot: per-thread partial over HB/NTF bins -> shfl scan -> crossing
__device__ __forceinline__ void pivot_from_hist(unsigned* hist, SelSh* sh, int tid) {
    unsigned ps = 0;
    const int bbase = tid * (HB/NTF);
    #pragma unroll
    for (int j = 0; j < HB/NTF; j++) ps += hist[bbase + j];
    unsigned incl = ps;
    #pragma unroll
    for (int o = 1; o < 32; o <<= 1) {
        unsigned v = __shfl_up_sync(0xffffffffu, incl, o);
        if ((tid & 31) >= o) incl += v;
    }
    if ((tid & 31) == 31) sh->wsumu[tid >> 5] = incl;
    __syncthreads();
    if (tid < 16) {
        unsigned wv = sh->wsumu[tid];
        unsigned wincl = wv;
        #pragma unroll
        for (int o = 1; o < 16; o <<= 1) {
            unsigned v = __shfl_up_sync(0x0000ffffu, wincl, o);
            if (tid >= o) wincl += v;
        }
        sh->wsumu[tid] = wincl - wv;   // exclusive warp offset
    }
    __syncthreads();
    unsigned excl = (incl - ps) + sh->wsumu[tid >> 5];
    if (excl < KNN && excl + ps >= KNN) {
        unsigned c = excl; int bin = bbase;
        while (c + hist[bin] < KNN) { c += hist[bin]; bin++; }
        sh->pivotS = bin;
    }
    __syncthreads();
}

// exact top-KNN over sd/si[0..S): histogram (uniform or exponent bins) pivot,
// then exact (d2, idx) rank inside the pivot subset. Fills order[0..KNN).
__device__ __forceinline__ bool sel_topk(const float* sd, const int* si,
                                         unsigned* hist, SelSh* sh,
                                         int S, int tid, bool uniform, float scale) {
    for (int i = tid; i < HB; i += NTF) hist[i] = 0u;
    if (tid == 0) sh->nsub = 0u;
    __syncthreads();
    for (int s = tid; s < S; s += NTF) {
        float d = sd[s];
        int bin = uniform ? min(HB-1, (int)(d*scale)) : d2bin_exp(d);
        atomicAdd(&hist[bin], 1u);
    }
    __syncthreads();
    pivot_from_hist(hist, sh, tid);
    const int piv = sh->pivotS;
    for (int s = tid; s < S; s += NTF) {
        float d = sd[s];
        int bin = uniform ? min(HB-1, (int)(d*scale)) : d2bin_exp(d);
        if (bin <= piv) {
            unsigned u = atomicAdd(&sh->nsub, 1u);
            if (u < SUBCAP) sh->subSlot[u] = s;
        }
    }
    __syncthreads();
    bool ok = (sh->nsub <= SUBCAP);
    const int U = (int)min(sh->nsub, (unsigned)SUBCAP);
    for (int u = tid; u < U; u += NTF) {
        int slot = sh->subSlot[u];
        float d = sd[slot]; int id = si[slot];
        int rank = 0;
        for (int v = 0; v < U; v++) {
            int s2 = sh->subSlot[v];
            float dv = sd[s2];
            rank += (dv < d) || (dv == d && si[s2] < id);
        }
        if (rank < KNN) sh->order[rank] = slot;
    }
    __syncthreads();
    return ok;
}

// shuffle-based deterministic reduction over the KNN winners (threads < 128)
template<int VN>
__device__ __forceinline__ void red_knn(const double* vals, SelSh* sh, int tid) {
    #pragma unroll
    for (int q = 0; q < VN; q++) {
        double v = vals[q];
        #pragma unroll
        for (int o = 16; o > 0; o >>= 1)
            v += __shfl_down_sync(0xffffffffu, v, o);
        if ((tid & 31) == 0 && (tid >> 5) < 4) sh->wsumd[(tid>>5)*VN + q] = v;
    }
    __syncthreads();
    if (tid < VN)
        sh->accd[tid] = sh->wsumd[0*VN+tid] + sh->wsumd[1*VN+tid]
                      + sh->wsumd[2*VN+tid] + sh->wsumd[3*VN+tid];
    __syncthreads();
}

__device__ __forceinline__ void cov_store(const float* sx, const float* sy,
                                          const float* sz, SelSh* sh,
                                          int tid, int gb) {
    double X = 0.0, Y = 0.0, Z = 0.0;
    if (tid < KNN) { int o = sh->order[tid]; X = sx[o]; Y = sy[o]; Z = sz[o]; }
    double v[9] = {X, Y, Z, X*X, X*Y, X*Z, Y*Y, Y*Z, Z*Z};
    red_knn<9>(v, sh, tid);
    if (tid == 0) {
        const double K = (double)KNN;
        double ax = sh->accd[0]/K, ay = sh->accd[1]/K, az = sh->accd[2]/K;
        d_gcov[gb][0] = sh->accd[3]/K - ax*ax;
        d_gcov[gb][1] = sh->accd[4]/K - ax*ay;
        d_gcov[gb][2] = sh->accd[5]/K - ax*az;
        d_gcov[gb][3] = sh->accd[6]/K - ay*ay;
        d_gcov[gb][4] = sh->accd[7]/K - ay*az;
        d_gcov[gb][5] = sh->accd[8]/K - az*az;
    }
    __syncthreads();
}

// ===========================================================================
// K2: selfin. Select -> (rescue|brute if flagged) -> eig -> ticket -> output.
// ===========================================================================
__global__ void __launch_bounds__(NTF) selfin_kernel(const float* __restrict__ pts_all,
                                                     float* __restrict__ out) {
    extern __shared__ float dyn[];
    // select view
    float* sx = dyn;
    float* sy = sx + SELCAP;
    float* sz = sy + SELCAP;
    float* sd = sz + SELCAP;
    int*   si = (int*)(sd + SELCAP);
    unsigned* histS = (unsigned*)(si + SELCAP);
    // rescue/brute view (same dyn range, used only after select is finished)
    float* cX = dyn;
    float* cY = cX + FCAP;
    float* cZ = cY + FCAP;
    float* cD = cZ + FCAP;
    int*   cI = (int*)(cD + FCAP);
    unsigned* histF = (unsigned*)(cI + FCAP);

    __shared__ SelSh sh;
    __shared__ float dirsS[NGB][3];
    __shared__ float gmfS[NGB][3];

    const int tid = threadIdx.x;
    const int gb  = blockIdx.x;
    const int b = gb / NGRP, g = gb % NGRP;
    const float* __restrict__ pts = pts_all + (size_t)b * NPTS * 3;
    const float4* __restrict__ p4 = (const float4*)pts;
    const int ci = g * STRIDE;
    const float qx = pts[3*ci], qy = pts[3*ci+1], qz = pts[3*ci+2];
    const float Ta = d_Ta[gb];

    // ---------------- select phase ----------------
    if (tid < PTC) sh.offs[tid+1] = d_segcnt[gb][tid];
    __syncthreads();
    if (tid == 0) {
        unsigned o = 0; int bad = 0;
        sh.offs[0] = 0;
        for (int pc = 0; pc < PTC; pc++) {
            unsigned c = sh.offs[pc+1];
            if (c > SEGCAP) { bad = 1; c = SEGCAP; }
            o += c;
            sh.offs[pc+1] = o;
        }
        sh.gflag = (bad || o < KNN) ? 2 : 0;
    }
    __syncthreads();

    if (sh.gflag == 0) {
        const int S = (int)sh.offs[PTC];
        for (int pc = 0; pc < PTC; pc++) {
            unsigned base = sh.offs[pc], cnt = sh.offs[pc+1] - sh.offs[pc];
            for (unsigned u = tid; u < cnt; u += NTF) {
                float4 v = d_seg[gb][pc][u];
                sx[base+u] = v.x; sy[base+u] = v.y; sz[base+u] = v.z;
                si[base+u] = __float_as_int(v.w);
            }
        }
        __syncthreads();
        for (int s = tid; s < S; s += NTF) {
            float dx = sx[s]-qx, dy = sy[s]-qy, dz = sz[s]-qz;
            sd[s] = fmaf(dx, dx, fmaf(dy, dy, dz*dz));
        }
        __syncthreads();

        // pass 1 (survivors = ALL points < Ta, exact); uniform bins over [0,Ta)
        const float scale1 = (float)HB / Ta;
        if (!sel_topk(sd, si, histS, &sh, S, tid, true, scale1)) {
            if (tid == 0) sh.gflag = 2;
            __syncthreads();
        }
        if (sh.gflag == 0) {
            double X = 0.0, Y = 0.0, Z = 0.0;
            if (tid < KNN) { int o = sh.order[tid]; X = sx[o]; Y = sy[o]; Z = sz[o]; }
            double v3[3] = {X, Y, Z};
            red_knn<3>(v3, &sh, tid);
            if (tid == 0) {
                const double K = (double)KNN;
                double mx = sh.accd[0]/K, my = sh.accd[1]/K, mz = sh.accd[2]/K;
                d_gmean[gb][0] = mx; d_gmean[gb][1] = my; d_gmean[gb][2] = mz;
                float fmx = (float)mx, fmy = (float)my, fmz = (float)mz;
                double dxq = (double)fmx - (double)qx;
                double dyq = (double)fmy - (double)qy;
                double dzq = (double)fmz - (double)qz;
                sh.Dc = sqrt(dxq*dxq + dyq*dyq + dzq*dzq);
                sh.q2s[0] = fmx; sh.q2s[1] = fmy; sh.q2s[2] = fmz;
                double rT = sqrt((double)Ta);
                sh.q2s[3] = (float)((sh.Dc + rT)*(sh.Dc + rT) * 1.01);
            }
            __syncthreads();

            // pass 2 over survivors; uniform bins over [0, (Dc+rTa)^2*1.01)
            const float mxf = sh.q2s[0], myf = sh.q2s[1], mzf = sh.q2s[2];
            const float scale2 = (float)HB / fmaxf(sh.q2s[3], 1e-30f);
            __syncthreads();
            for (int s = tid; s < S; s += NTF) {
                float dx = sx[s]-mxf, dy = sy[s]-myf, dz = sz[s]-mzf;
                sd[s] = fmaf(dx, dx, fmaf(dy, dy, dz*dz));
            }
            __syncthreads();
            if (!sel_topk(sd, si, histS, &sh, S, tid, true, scale2)) {
                if (tid == 0) sh.gflag = 2;
                __syncthreads();
            }
            if (sh.gflag == 0) {
                if (tid == 0) {
                    float d100 = sd[sh.order[KNN-1]];
                    double lhs = sh.Dc + sqrt((double)d100);
                    if (lhs*lhs*(1.0 + 1e-4) < (double)Ta) {
                        sh.gflag = 0;
                    } else {
                        sh.gflag = 1;
                        sh.sT2 = d100;
                    }
                }
                __syncthreads();
                if (sh.gflag == 0) cov_store(sx, sy, sz, &sh, tid, gb);
            }
        }
    }
    __syncthreads();

    // ---------------- rescue (flag 1): exact ball over whole cloud ----------
    if (sh.gflag == 1) {
        const float mxf = sh.q2s[0], myf = sh.q2s[1], mzf = sh.q2s[2];
        const float T2 = sh.sT2;
        __syncthreads();   // protect dyn reuse
        if (tid == 0) sh.ncand = 0u;
        __syncthreads();
        #pragma unroll 2
        for (int it = tid; it < NPTS/4; it += NTF) {
            float4 A = p4[3*it+0], B = p4[3*it+1], C = p4[3*it+2];
            float xs[4] = {A.x, A.w, B.z, C.y};
            float ys[4] = {A.y, B.x, B.w, C.z};
            float zs[4] = {A.z, B.y, C.x, C.w};
            #pragma unroll
            for (int k = 0; k < 4; k++) {
                float dx = xs[k]-mxf, dy = ys[k]-myf, dz = zs[k]-mzf;
                float d2 = fmaf(dx, dx, fmaf(dy, dy, dz*dz));
                if (d2 <= T2) {
                    unsigned s = atomicAdd(&sh.ncand, 1u);
                    if (s < FCAP) {
                        cX[s] = xs[k]; cY[s] = ys[k]; cZ[s] = zs[k];
                        cD[s] = d2; cI[s] = 4*it + k;
                    }
                }
            }
        }
        __syncthreads();
        if (sh.ncand > FCAP) { if (tid == 0) sh.gflag = 2; __syncthreads(); }
        else {
            int C = (int)sh.ncand;
            float scaleR = (float)HB / fmaxf(T2 * 1.0001f, 1e-30f);
            sel_topk(cD, cI, histF, &sh, C, tid, true, scaleR);
            cov_store(cX, cY, cZ, &sh, tid, gb);
        }
    }

    // ---------------- brute (flag 2): exact full fallback -------------------
    if (sh.gflag == 2) {
        __syncthreads();
        for (int i = tid; i < HB; i += NTF) histF[i] = 0u;
        __syncthreads();
        for (int it = tid; it < NPTS/4; it += NTF) {
            float4 A = p4[3*it+0], B = p4[3*it+1], C = p4[3*it+2];
            float xs[4] = {A.x, A.w, B.z, C.y};
            float ys[4] = {A.y, B.x, B.w, C.z};
            float zs[4] = {A.z, B.y, C.x, C.w};
            #pragma unroll
            for (int k = 0; k < 4; k++) {
                float dx = xs[k]-qx, dy = ys[k]-qy, dz = zs[k]-qz;
                atomicAdd(&histF[d2bin_exp(fmaf(dx, dx, fmaf(dy, dy, dz*dz)))], 1u);
            }
        }
        __syncthreads();
        pivot_from_hist(histF, &sh, tid);
        const float edge1 = __uint_as_float(((unsigned)sh.pivotS + 1u) << 21);
        if (tid == 0) sh.ncand = 0u;
        __syncthreads();
        for (int it = tid; it < NPTS/4; it += NTF) {
            float4 A = p4[3*it+0], B = p4[3*it+1], C = p4[3*it+2];
            float xs[4] = {A.x, A.w, B.z, C.y};
            float ys[4] = {A.y, B.x, B.w, C.z};
            float zs[4] = {A.z, B.y, C.x, C.w};
            #pragma unroll
            for (int k = 0; k < 4; k++) {
                float dx = xs[k]-qx, dy = ys[k]-qy, dz = zs[k]-qz;
                float d2 = fmaf(dx, dx, fmaf(dy, dy, dz*dz));
                if (d2 < edge1) {
                    unsigned s = atomicAdd(&sh.ncand, 1u);
                    if (s < FCAP) {
                        cX[s] = xs[k]; cY[s] = ys[k]; cZ[s] = zs[k];
                        cD[s] = d2; cI[s] = 4*it + k;
                    }
                }
            }
        }
        __syncthreads();
        int C1 = (int)min(sh.ncand, (unsigned)FCAP);
        sel_topk(cD, cI, histF, &sh, C1, tid, false, 0.0f);
        {
            double X = 0.0, Y = 0.0, Z = 0.0;
            if (tid < KNN) { int o = sh.order[tid]; X = cX[o]; Y = cY[o]; Z = cZ[o]; }
            double v3[3] = {X, Y, Z};
            red_knn<3>(v3, &sh, tid);
        }
        if (tid == 0) {
            const double K = (double)KNN;
            double mx = sh.accd[0]/K, my = sh.accd[1]/K, mz = sh.accd[2]/K;
            d_gmean[gb][0] = mx; d_gmean[gb][1] = my; d_gmean[gb][2] = mz;
            double dxq = mx - (double)qx, dyq = my - (double)qy, dzq = mz - (double)qz;
            double D  = sqrt(dxq*dxq + dyq*dyq + dzq*dzq);
            double r1 = sqrt((double)edge1);
            double R  = 2.0*D + r1;
            sh.q2s[0] = (float)mx; sh.q2s[1] = (float)my; sh.q2s[2] = (float)mz;
            sh.q2s[3] = (float)(R*R) * 1.0002f;
        }
        __syncthreads();
        const float q2x = sh.q2s[0], q2y = sh.q2s[1], q2z = sh.q2s[2];
        const float T2c = sh.q2s[3];
        __syncthreads();
        if (tid == 0) sh.ncand = 0u;
        __syncthreads();
        for (int it = tid; it < NPTS/4; it += NTF) {
            float4 A = p4[3*it+0], B = p4[3*it+1], C = p4[3*it+2];
            float xs[4] = {A.x, A.w, B.z, C.y};
            float ys[4] = {A.y, B.x, B.w, C.z};
            float zs[4] = {A.z, B.y, C.x, C.w};
            #pragma unroll
            for (int k = 0; k < 4; k++) {
                float dx = xs[k]-qx, dy = ys[k]-qy, dz = zs[k]-qz;
                float d2c = fmaf(dx, dx, fmaf(dy, dy, dz*dz));
                if (d2c < T2c) {
                    float ex = xs[k]-q2x, ey = ys[k]-q2y, ez = zs[k]-q2z;
                    float d2m = fmaf(ex, ex, fmaf(ey, ey, ez*ez));
                    unsigned s = atomicAdd(&sh.ncand, 1u);
                    if (s < FCAP) {
                        cX[s] = xs[k]; cY[s] = ys[k]; cZ[s] = zs[k];
                        cD[s] = d2m; cI[s] = 4*it + k;
                    }
                }
            }
        }
        __syncthreads();
        int C2 = (int)min(sh.ncand, (unsigned)FCAP);
        sel_topk(cD, cI, histF, &sh, C2, tid, false, 0.0f);
        cov_store(cX, cY, cZ, &sh, tid, gb);
    }
    __syncthreads();

    // ---------------- eigensolve ----------------
    if (tid == 0) {
        double a00 = d_gcov[gb][0], a01 = d_gcov[gb][1], a02 = d_gcov[gb][2];
        double a11 = d_gcov[gb][3], a12 = d_gcov[gb][4], a22 = d_gcov[gb][5];
        double q  = (a00 + a11 + a22) / 3.0;
        double p1 = a01*a01 + a02*a02 + a12*a12;
        double b00 = a00 - q, b11 = a11 - q, b22 = a22 - q;
        double p2 = b00*b00 + b11*b11 + b22*b22 + 2.0*p1;
        double l1, l2, l3;
        if (p2 < 1e-60) {
            l1 = l2 = l3 = q;
        } else {
            double p  = sqrt(p2 / 6.0);
            double ip = 1.0 / p;
            double c00 = b00*ip, c11 = b11*ip, c22 = b22*ip;
            double c01 = a01*ip, c02 = a02*ip, c12 = a12*ip;
            double detB = c00*(c11*c22 - c12*c12)
                        - c01*(c01*c22 - c12*c02)
                        + c02*(c01*c12 - c11*c02);
            double r = 0.5 * detB;
            r = fmin(1.0, fmax(-1.0, r));
            double phi = (double)acosf((float)r) * (1.0/3.0);
            l3 = q + 2.0*p*(double)cosf((float)phi);
            l1 = q + 2.0*p*(double)cosf((float)(phi + 2.0943951023931953));
            l2 = 3.0*q - l1 - l3;
        }
        double denom = l1 + l2 + l3 + 1e-9;
        d_fs[gb] = (l3 - l2) / denom;

        double r0x = a00 - l3, r0y = a01,      r0z = a02;
        double r1x = a01,      r1y = a11 - l3, r1z = a12;
        double r2x = a02,      r2y = a12,      r2z = a22 - l3;
        double vax = r0y*r1z - r0z*r1y, vay = r0z*r1x - r0x*r1z, vaz = r0x*r1y - r0y*r1x;
        double vbx = r1y*r2z - r1z*r2y, vby = r1z*r2x - r1x*r2z, vbz = r1x*r2y - r1y*r2x;
        double vcx = r2y*r0z - r2z*r0y, vcy = r2z*r0x - r2x*r0z, vcz = r2x*r0y - r2y*r0x;
        double na = vax*vax + vay*vay + vaz*vaz;
        double nb = vbx*vbx + vby*vby + vbz*vbz;
        double nc = vcx*vcx + vcy*vcy + vcz*vcz;
        double vx2, vy2, vz2, nn;
        if (na >= nb && na >= nc) { vx2 = vax; vy2 = vay; vz2 = vaz; nn = na; }
        else if (nb >= nc)        { vx2 = vbx; vy2 = vby; vz2 = vbz; nn = nb; }
        else                      { vx2 = vcx; vy2 = vcy; vz2 = vcz; nn = nc; }
        if (nn < 1e-300) { vx2 = 0.0; vy2 = 0.0; vz2 = 1.0; nn = 1.0; }
        // fast inverse-sqrt: float estimate + one double Newton step (~1e-14 rel)
        double inn = (double)rsqrtf((float)nn);
        inn = inn * (1.5 - 0.5 * nn * inn * inn);
        d_dirs[gb][0] = (float)(vx2 * inn);
        d_dirs[gb][1] = (float)(vy2 * inn);
        d_dirs[gb][2] = (float)(vz2 * inn);
    }
    __syncthreads();

    // ---------------- ticket: last block reduces the output ----------------
    if (tid == 0) {
        __threadfence();
        unsigned t = atomicAdd(&d_ticket, 1u);
        sh.lastb = (t == NGB - 1) ? 1 : 0;
    }
    __syncthreads();
    if (!sh.lastb) return;
    __threadfence();

    double fs = 0.0;
    if (tid < NGB) {
        fs = d_fs[tid];
        dirsS[tid][0] = d_dirs[tid][0];
        dirsS[tid][1] = d_dirs[tid][1];
        dirsS[tid][2] = d_dirs[tid][2];
        gmfS[tid][0] = (float)d_gmean[tid][0];
        gmfS[tid][1] = (float)d_gmean[tid][1];
        gmfS[tid][2] = (float)d_gmean[tid][2];
    }
    __syncthreads();

    double term = 0.0;
    if (tid < NGB) {
        int bb = tid / NGRP, gg = tid % NGRP;
        float qx2 = gmfS[tid][0], qy2 = gmfS[tid][1], qz2 = gmfS[tid][2];
        float best = 3.4e38f; int bj = 0;
        for (int o = 0; o < NGRP; o++) {
            float dx = qx2 - gmfS[bb*NGRP+o][0];
            float dy = qy2 - gmfS[bb*NGRP+o][1];
            float dz = qz2 - gmfS[bb*NGRP+o][2];
            float dd = dx*dx + dy*dy + dz*dz;
            if (o == gg) dd += 1e30f;
            if (dd < best) { best = dd; bj = o; }
        }
        int j = bb*NGRP + bj;
        float cs = dirsS[tid][0]*dirsS[j][0] + dirsS[tid][1]*dirsS[j][1] + dirsS[tid][2]*dirsS[j][2];
        term = 1.0 - (double)cs * (double)cs;
    }

    double sumfs = tree_red(sh.red, tid, fs);
    double sumterm = tree_red(sh.red, tid, term);
    if (tid == 0) out[0] = (float)(-sumfs / (double)NBATCH + sumterm / (double)NGB);
}

extern "C" void kernel_launch(void* const* d_in, const int* in_sizes, int n_in,
                              void* d_out, int out_size) {
    const float* pts = (const float*)d_in[0];
    float* out = (float*)d_out;
    cudaFuncSetAttribute(selfin_kernel, cudaFuncAttributeMaxDynamicSharedMemorySize, SF_DYN);
    scan_kernel<<<NBATCH*GT*PTC, NT>>>(pts);
    selfin_kernel<<<NGB, NTF, SF_DYN>>>(pts, out);
}